// round 13
// baseline (speedup 1.0000x reference)
#include <cuda_runtime.h>
#include <cstdint>

// Problem constants (match reference)
#define IMG_H 256
#define IMG_W 256
#define NB    8
#define NP    65536
#define EPSF  1e-5f

#define HW  (IMG_H * IMG_W)
#define BHW (NB * HW)              // 524288
#define BN  (NB * NP)              // 524288

// z encoding: enc(z) = ~bits(z). For positive z, enc is strictly DEcreasing,
// so max(enc) == min(z), and 0 is a natural "empty" value -> zero-init device
// globals cover the first call; scratch is re-zeroed each call for replays.
__device__ unsigned int g_pm[BHW];     // per-pixel max of enc(z); 0 = empty
__device__ unsigned int g_zenc[BHW];   // 5x5 max-filtered enc (fully overwritten)

// Interleaved (wz, w) accumulator with 4-float4 front/back padding so vector
// atomics whose zero-weight pad lanes fall outside a row can never leave the
// array (they add exactly +0.0f wherever they land).
__device__ float4 g_dw4[BHW / 2 + 8];  // [4 pad | BHW/2 data | 4 pad]
#define DW_BASE ((float2*)g_dw4 + 8)   // float2 view of data region (16B aligned)

__device__ __forceinline__ float fast_rcp(float x) {
    float r;
    asm("rcp.approx.f32 %0, %1;" : "=f"(r) : "f"(x));
    return r;
}

// ---------------------------------------------------------------------------
// Pass 1: per-pixel scatter-min, 4 points per thread (3x LDG.128)
// ---------------------------------------------------------------------------
__global__ void scatter_pm_kernel(const float4* __restrict__ pts4) {
    int idx = blockIdx.x * blockDim.x + threadIdx.x;
    if (idx >= BN / 4) return;
    float4 a = pts4[3 * idx + 0];
    float4 b = pts4[3 * idx + 1];
    float4 c = pts4[3 * idx + 2];
    unsigned int* pm = g_pm + (idx >> 14) * HW;   // batch = (4*idx)/NP

    float xs[4] = {a.x, a.w, b.z, c.y};
    float ys[4] = {a.y, b.x, b.w, c.z};
    float zs[4] = {a.z, b.y, c.x, c.w};
    #pragma unroll
    for (int k = 0; k < 4; k++) {
        int px = (int)rintf(xs[k]);   // round-half-even == jnp.round
        int py = (int)rintf(ys[k]);
        if (px < 0 || px >= IMG_W || py < 0 || py >= IMG_H) continue;
        atomicMax(&pm[py * IMG_W + px], ~__float_as_uint(zs[k]));
    }
}

// ---------------------------------------------------------------------------
// Pass 2: 5x5 max-filter (== 5x5 min-erosion of z), separable in smem tiles
// ---------------------------------------------------------------------------
#define TILE 32
__global__ void minfilter_kernel() {
    __shared__ unsigned int s[36][36 + 1];
    __shared__ unsigned int h[36][TILE + 1];

    int b  = blockIdx.z;
    int ox = blockIdx.x * TILE;
    int oy = blockIdx.y * TILE;
    const unsigned int* pm = g_pm + b * HW;
    int t = threadIdx.y * blockDim.x + threadIdx.x;  // 256 threads

    for (int i = t; i < 36 * 36; i += 256) {
        int r = i / 36, c = i % 36;
        int gy = oy + r - 2, gx = ox + c - 2;
        unsigned int v = 0;  // OOB -> empty (identity for max)
        if (gy >= 0 && gy < IMG_H && gx >= 0 && gx < IMG_W) v = pm[gy * IMG_W + gx];
        s[r][c] = v;
    }
    __syncthreads();

    for (int i = t; i < 36 * TILE; i += 256) {
        int r = i / TILE, c = i % TILE;
        unsigned int v = s[r][c];
        v = max(v, s[r][c + 1]);
        v = max(v, s[r][c + 2]);
        v = max(v, s[r][c + 3]);
        v = max(v, s[r][c + 4]);
        h[r][c] = v;
    }
    __syncthreads();

    unsigned int* zo = g_zenc + b * HW;
    for (int i = t; i < TILE * TILE; i += 256) {
        int r = i / TILE, c = i % TILE;
        unsigned int v = h[r][c];
        v = max(v, h[r + 1][c]);
        v = max(v, h[r + 2][c]);
        v = max(v, h[r + 3][c]);
        v = max(v, h[r + 4][c]);
        zo[(oy + r) * IMG_W + (ox + c)] = v;
    }
}

// ---------------------------------------------------------------------------
// Pass 3 (FUSED vis + splat): each thread computes visibility for 4 points
// and writes vis_out; then the warp iterates the ballot of visible points,
// broadcasting each one's (x,y,z) via shfl, and ALL 32 lanes execute the
// splat cooperatively: lane = (row 0..7, quarter 0..3), rows 0..6 live, each
// active lane issues exactly ONE RED.128 covering its 2-pixel quarter of the
// even-aligned 8-col window. No compaction list, no extra launch.
// bb is warp-uniform (batch boundaries at multiples of 16384 idx).
// Weights via rcp.approx (rel err ~1e-7 << 1e-3 threshold). Zero-weight pad
// lanes add +0.0f; array padding absorbs overreach.
// Tail: re-zeroes g_pm for the next graph replay.
// ---------------------------------------------------------------------------
__global__ void vis_splat_kernel(const float4* __restrict__ pts4,
                                 const float* __restrict__ thr_p,
                                 float4* __restrict__ vis_out4) {
    // Grid is sized EXACTLY BN/4 threads: all lanes of every warp are live.
    int idx = blockIdx.x * blockDim.x + threadIdx.x;
    float4 a = pts4[3 * idx + 0];
    float4 b = pts4[3 * idx + 1];
    float4 c = pts4[3 * idx + 2];
    float thr = __ldg(thr_p);
    int bb = idx >> 14;                      // warp-uniform
    const unsigned int* ze = g_zenc + bb * HW;

    float xs[4] = {a.x, a.w, b.z, c.y};
    float ys[4] = {a.y, b.x, b.w, c.z};
    float zs[4] = {a.z, b.y, c.x, c.w};
    bool vis[4];
    #pragma unroll
    for (int k = 0; k < 4; k++) {
        int px = (int)rintf(xs[k]);
        int py = (int)rintf(ys[k]);
        bool in_img = (px >= 0) && (px < IMG_W) && (py >= 0) && (py < IMG_H);
        bool v = false;
        if (in_img) {
            float zmin = __uint_as_float(~ze[py * IMG_W + px]);
            v = (zs[k] <= zmin + thr);
        }
        vis[k] = v;
    }
    vis_out4[idx] = make_float4(vis[0] ? 1.f : 0.f, vis[1] ? 1.f : 0.f,
                                vis[2] ? 1.f : 0.f, vis[3] ? 1.f : 0.f);

    // --- warp-cooperative splat of this warp's visible points ---
    int lane = threadIdx.x & 31;
    int row  = lane >> 2;                    // 0..7 (row 7 idle)
    int q    = lane & 3;                     // quarter: 2 pixels
    float2* dwb = DW_BASE + bb * HW;

    #pragma unroll
    for (int k = 0; k < 4; k++) {
        unsigned int mask = __ballot_sync(0xFFFFFFFFu, vis[k]);
        while (mask) {
            int src = __ffs(mask) - 1;
            mask &= mask - 1u;
            float x = __shfl_sync(0xFFFFFFFFu, xs[k], src);
            float y = __shfl_sync(0xFFFFFFFFu, ys[k], src);
            float z = __shfl_sync(0xFFFFFFFFu, zs[k], src);
            int px = (int)rintf(x);
            int py = (int)rintf(y);
            int ii = py + row - 3;
            if (row < 7 && ii >= 0 && ii < IMG_H) {
                float dy = y - (float)ii;
                float dy2 = dy * dy;
                int jstart = ((px - 3) & ~1) + 2 * q;   // lane's 2-col window
                float dx0 = x - (float)jstart;
                float dx1 = dx0 - 1.0f;
                int j0 = jstart, j1 = jstart + 1;
                bool ok0 = (j0 >= px - 3) && (j0 <= px + 3) && (j0 >= 0) && (j0 < IMG_W);
                bool ok1 = (j1 >= px - 3) && (j1 <= px + 3) && (j1 >= 0) && (j1 < IMG_W);
                float w0 = ok0 ? fast_rcp(dx0 * dx0 + dy2 + EPSF) : 0.0f;
                float w1 = ok1 ? fast_rcp(dx1 * dx1 + dy2 + EPSF) : 0.0f;
                atomicAdd((float4*)(dwb + ii * IMG_W + jstart),
                          make_float4(w0 * z, w0, w1 * z, w1));
            }
        }
    }

    // Tail: reset g_pm (already consumed by minfilter this call).
    uint4 zu = make_uint4(0u, 0u, 0u, 0u);
    int stride = gridDim.x * blockDim.x;
    for (int j = idx; j < BHW / 4; j += stride) {
        ((uint4*)g_pm)[j] = zu;
    }
}

// ---------------------------------------------------------------------------
// Pass 4: de-interleave accumulator (8 px/thread, MLP=4) + reset dw scratch
// ---------------------------------------------------------------------------
__global__ void finish_kernel(float* __restrict__ out) {
    int i = blockIdx.x * blockDim.x + threadIdx.x;  // one thread = 8 pixels
    if (i >= BHW / 8) return;
    const float4* dw = (const float4*)DW_BASE;      // 16B aligned
    float4 f0 = dw[4 * i + 0];
    float4 f1 = dw[4 * i + 1];
    float4 f2 = dw[4 * i + 2];
    float4 f3 = dw[4 * i + 3];
    ((float4*)out)[2 * i + 0]         = make_float4(f0.x, f0.z, f1.x, f1.z);  // depth
    ((float4*)out)[2 * i + 1]         = make_float4(f2.x, f2.z, f3.x, f3.z);
    ((float4*)(out + BHW))[2 * i + 0] = make_float4(f0.y, f0.w, f1.y, f1.w);  // weight
    ((float4*)(out + BHW))[2 * i + 1] = make_float4(f2.y, f2.w, f3.y, f3.w);
    float4 zf = make_float4(0.f, 0.f, 0.f, 0.f);
    ((float4*)DW_BASE)[4 * i + 0] = zf;
    ((float4*)DW_BASE)[4 * i + 1] = zf;
    ((float4*)DW_BASE)[4 * i + 2] = zf;
    ((float4*)DW_BASE)[4 * i + 3] = zf;
}

// ---------------------------------------------------------------------------
extern "C" void kernel_launch(void* const* d_in, const int* in_sizes, int n_in,
                              void* d_out, int out_size) {
    const float* pts = (const float*)d_in[0];   // [B, N, 3]
    const float* thr = (const float*)d_in[1];   // scalar
    float* out = (float*)d_out;                 // [depth | weight | is_visible]

    const int T = 256;
    scatter_pm_kernel<<<BN / 4 / T, T>>>((const float4*)pts);
    dim3 fgrid(IMG_W / TILE, IMG_H / TILE, NB);
    minfilter_kernel<<<fgrid, dim3(32, 8)>>>();
    vis_splat_kernel<<<BN / 4 / T, T>>>((const float4*)pts, thr,
                                        (float4*)(out + 2 * BHW));
    finish_kernel<<<BHW / 8 / T, T>>>(out);
}

// round 14
// speedup vs baseline: 1.0323x; 1.0323x over previous
#include <cuda_runtime.h>
#include <cstdint>

// Problem constants (match reference)
#define IMG_H 256
#define IMG_W 256
#define NB    8
#define NP    65536
#define EPSF  1e-5f

#define HW  (IMG_H * IMG_W)
#define BHW (NB * HW)              // 524288
#define BN  (NB * NP)              // 524288

// z encoding: enc(z) = ~bits(z). For positive z, enc is strictly DEcreasing,
// so max(enc) == min(z), and 0 is a natural "empty" value -> zero-init device
// globals cover the first call; scratch is re-zeroed each call for replays.
__device__ unsigned int g_pm[BHW];     // per-pixel max of enc(z); 0 = empty
__device__ unsigned int g_zenc[BHW];   // 5x5 max-filtered enc (fully overwritten)

// Interleaved (wz, w) accumulator with 4-float4 front/back padding so vector
// atomics whose zero-weight pad lanes fall outside a row can never leave the
// array (they add exactly +0.0f wherever they land; pad is never read/reset).
__device__ float4 g_dw4[BHW / 2 + 8];  // [4 pad | BHW/2 data | 4 pad]
#define DW_BASE ((float2*)g_dw4 + 8)   // float2 view of data region (16B aligned)

__device__ __forceinline__ float fast_rcp(float x) {
    float r;
    asm("rcp.approx.f32 %0, %1;" : "=f"(r) : "f"(x));
    return r;
}

// ---------------------------------------------------------------------------
// Pass 1: per-pixel scatter-min, 4 points per thread (3x LDG.128).
// Tail: zero the dw accumulator for THIS call's splat (runs before vis_splat
// in program order; previous call's finish already consumed the old values).
// ---------------------------------------------------------------------------
__global__ void scatter_pm_kernel(const float4* __restrict__ pts4) {
    int idx = blockIdx.x * blockDim.x + threadIdx.x;
    if (idx < BN / 4) {
        float4 a = pts4[3 * idx + 0];
        float4 b = pts4[3 * idx + 1];
        float4 c = pts4[3 * idx + 2];
        unsigned int* pm = g_pm + (idx >> 14) * HW;   // batch = (4*idx)/NP

        float xs[4] = {a.x, a.w, b.z, c.y};
        float ys[4] = {a.y, b.x, b.w, c.z};
        float zs[4] = {a.z, b.y, c.x, c.w};
        #pragma unroll
        for (int k = 0; k < 4; k++) {
            int px = (int)rintf(xs[k]);   // round-half-even == jnp.round
            int py = (int)rintf(ys[k]);
            if (px < 0 || px >= IMG_W || py < 0 || py >= IMG_H) continue;
            atomicMax(&pm[py * IMG_W + px], ~__float_as_uint(zs[k]));
        }
    }

    // Tail: reset dw data region (4 MB) for this call's splat.
    float4 zf = make_float4(0.f, 0.f, 0.f, 0.f);
    int stride = gridDim.x * blockDim.x;
    float4* dwq = (float4*)DW_BASE;
    for (int j = idx; j < BHW / 2; j += stride) {
        dwq[j] = zf;
    }
}

// ---------------------------------------------------------------------------
// Pass 2: 5x5 max-filter (== 5x5 min-erosion of z), separable in smem tiles
// ---------------------------------------------------------------------------
#define TILE 32
__global__ void minfilter_kernel() {
    __shared__ unsigned int s[36][36 + 1];
    __shared__ unsigned int h[36][TILE + 1];

    int b  = blockIdx.z;
    int ox = blockIdx.x * TILE;
    int oy = blockIdx.y * TILE;
    const unsigned int* pm = g_pm + b * HW;
    int t = threadIdx.y * blockDim.x + threadIdx.x;  // 256 threads

    for (int i = t; i < 36 * 36; i += 256) {
        int r = i / 36, c = i % 36;
        int gy = oy + r - 2, gx = ox + c - 2;
        unsigned int v = 0;  // OOB -> empty (identity for max)
        if (gy >= 0 && gy < IMG_H && gx >= 0 && gx < IMG_W) v = pm[gy * IMG_W + gx];
        s[r][c] = v;
    }
    __syncthreads();

    for (int i = t; i < 36 * TILE; i += 256) {
        int r = i / TILE, c = i % TILE;
        unsigned int v = s[r][c];
        v = max(v, s[r][c + 1]);
        v = max(v, s[r][c + 2]);
        v = max(v, s[r][c + 3]);
        v = max(v, s[r][c + 4]);
        h[r][c] = v;
    }
    __syncthreads();

    unsigned int* zo = g_zenc + b * HW;
    for (int i = t; i < TILE * TILE; i += 256) {
        int r = i / TILE, c = i % TILE;
        unsigned int v = h[r][c];
        v = max(v, h[r + 1][c]);
        v = max(v, h[r + 2][c]);
        v = max(v, h[r + 3][c]);
        v = max(v, h[r + 4][c]);
        zo[(oy + r) * IMG_W + (ox + c)] = v;
    }
}

// ---------------------------------------------------------------------------
// Pass 3 (FUSED vis + splat): each thread computes visibility for 4 points
// and writes vis_out; then the warp iterates the ballot of visible points,
// broadcasting each one's (x,y,z) via shfl, and ALL 32 lanes execute the
// splat cooperatively: lane = (row 0..7, quarter 0..3), rows 0..6 live, each
// active lane issues exactly ONE RED.128 covering its 2-pixel quarter of the
// even-aligned 8-col window. bb is warp-uniform (batch boundaries at
// multiples of 16384 idx). Weights via rcp.approx (rel err ~1e-7 << 1e-3
// threshold). Zero-weight pad lanes add +0.0f; array padding absorbs
// overreach. Tail: re-zeroes g_pm for the next graph replay.
// ---------------------------------------------------------------------------
__global__ void vis_splat_kernel(const float4* __restrict__ pts4,
                                 const float* __restrict__ thr_p,
                                 float4* __restrict__ vis_out4) {
    // Grid is sized EXACTLY BN/4 threads: all lanes of every warp are live.
    int idx = blockIdx.x * blockDim.x + threadIdx.x;
    float4 a = pts4[3 * idx + 0];
    float4 b = pts4[3 * idx + 1];
    float4 c = pts4[3 * idx + 2];
    float thr = __ldg(thr_p);
    int bb = idx >> 14;                      // warp-uniform
    const unsigned int* ze = g_zenc + bb * HW;

    float xs[4] = {a.x, a.w, b.z, c.y};
    float ys[4] = {a.y, b.x, b.w, c.z};
    float zs[4] = {a.z, b.y, c.x, c.w};
    bool vis[4];
    #pragma unroll
    for (int k = 0; k < 4; k++) {
        int px = (int)rintf(xs[k]);
        int py = (int)rintf(ys[k]);
        bool in_img = (px >= 0) && (px < IMG_W) && (py >= 0) && (py < IMG_H);
        bool v = false;
        if (in_img) {
            float zmin = __uint_as_float(~ze[py * IMG_W + px]);
            v = (zs[k] <= zmin + thr);
        }
        vis[k] = v;
    }
    vis_out4[idx] = make_float4(vis[0] ? 1.f : 0.f, vis[1] ? 1.f : 0.f,
                                vis[2] ? 1.f : 0.f, vis[3] ? 1.f : 0.f);

    // --- warp-cooperative splat of this warp's visible points ---
    int lane = threadIdx.x & 31;
    int row  = lane >> 2;                    // 0..7 (row 7 idle)
    int q    = lane & 3;                     // quarter: 2 pixels
    float2* dwb = DW_BASE + bb * HW;

    #pragma unroll
    for (int k = 0; k < 4; k++) {
        unsigned int mask = __ballot_sync(0xFFFFFFFFu, vis[k]);
        while (mask) {
            int src = __ffs(mask) - 1;
            mask &= mask - 1u;
            float x = __shfl_sync(0xFFFFFFFFu, xs[k], src);
            float y = __shfl_sync(0xFFFFFFFFu, ys[k], src);
            float z = __shfl_sync(0xFFFFFFFFu, zs[k], src);
            int px = (int)rintf(x);
            int py = (int)rintf(y);
            int ii = py + row - 3;
            if (row < 7 && ii >= 0 && ii < IMG_H) {
                float dy = y - (float)ii;
                float dy2 = dy * dy;
                int jstart = ((px - 3) & ~1) + 2 * q;   // lane's 2-col window
                float dx0 = x - (float)jstart;
                float dx1 = dx0 - 1.0f;
                int j0 = jstart, j1 = jstart + 1;
                bool ok0 = (j0 >= px - 3) && (j0 <= px + 3) && (j0 >= 0) && (j0 < IMG_W);
                bool ok1 = (j1 >= px - 3) && (j1 <= px + 3) && (j1 >= 0) && (j1 < IMG_W);
                float w0 = ok0 ? fast_rcp(dx0 * dx0 + dy2 + EPSF) : 0.0f;
                float w1 = ok1 ? fast_rcp(dx1 * dx1 + dy2 + EPSF) : 0.0f;
                atomicAdd((float4*)(dwb + ii * IMG_W + jstart),
                          make_float4(w0 * z, w0, w1 * z, w1));
            }
        }
    }

    // Tail: reset g_pm (already consumed by minfilter this call).
    uint4 zu = make_uint4(0u, 0u, 0u, 0u);
    int stride = gridDim.x * blockDim.x;
    for (int j = idx; j < BHW / 4; j += stride) {
        ((uint4*)g_pm)[j] = zu;
    }
}

// ---------------------------------------------------------------------------
// Pass 4: de-interleave accumulator into output planes. 4 px/thread,
// grid 512 (vs 256 before: the 8px/thread version starved the SMs at 17%
// occupancy). Pure read 4MB + write 4MB; dw reset now lives in scatter's tail.
// ---------------------------------------------------------------------------
__global__ void finish_kernel(float* __restrict__ out) {
    int i = blockIdx.x * blockDim.x + threadIdx.x;  // one thread = 4 pixels
    if (i >= BHW / 4) return;
    const float4* dw = (const float4*)DW_BASE;      // 16B aligned
    float4 f0 = dw[2 * i + 0];                      // (wz0, w0, wz1, w1)
    float4 f1 = dw[2 * i + 1];                      // (wz2, w2, wz3, w3)
    ((float4*)out)[i]         = make_float4(f0.x, f0.z, f1.x, f1.z);  // depth
    ((float4*)(out + BHW))[i] = make_float4(f0.y, f0.w, f1.y, f1.w);  // weight
}

// ---------------------------------------------------------------------------
extern "C" void kernel_launch(void* const* d_in, const int* in_sizes, int n_in,
                              void* d_out, int out_size) {
    const float* pts = (const float*)d_in[0];   // [B, N, 3]
    const float* thr = (const float*)d_in[1];   // scalar
    float* out = (float*)d_out;                 // [depth | weight | is_visible]

    const int T = 256;
    scatter_pm_kernel<<<BN / 4 / T, T>>>((const float4*)pts);
    dim3 fgrid(IMG_W / TILE, IMG_H / TILE, NB);
    minfilter_kernel<<<fgrid, dim3(32, 8)>>>();
    vis_splat_kernel<<<BN / 4 / T, T>>>((const float4*)pts, thr,
                                        (float4*)(out + 2 * BHW));
    finish_kernel<<<BHW / 4 / T, T>>>(out);
}